// round 13
// baseline (speedup 1.0000x reference)
#include <cuda_runtime.h>
#include <cuda_bf16.h>
#include <cstdint>

#define PLANES 80
#define FLAT   5120      // 80 * 64
#define NMOVES 1858
#define BATCH  16384
#define ROW_BYTES (FLAT * 4)   // 20480
#define NSCAN  929             // scan blocks: 929 x 256 thr x 5 x 32B = 38,051,840 B exactly

// move -> flat-index map, rebuilt every launch.
__device__ __align__(16) int g_idx[NMOVES];
// zero-initialized; self-reset at end of every launch (no memset node needed)
__device__ unsigned int g_done;     // scan tiles published
__device__ unsigned int g_passed;   // blocks past the wait

// ---------------------------------------------------------------------------
// PTX helpers
// ---------------------------------------------------------------------------
__device__ __forceinline__ uint32_t smem_u32(const void* p) {
    uint32_t a;
    asm("{ .reg .u64 t; cvta.to.shared.u64 t, %1; cvt.u32.u64 %0, t; }"
        : "=r"(a) : "l"(p));
    return a;
}
__device__ __forceinline__ void mbar_init(uint32_t addr, uint32_t count) {
    asm volatile("mbarrier.init.shared.b64 [%0], %1;" :: "r"(addr), "r"(count) : "memory");
}
__device__ __forceinline__ void mbar_expect_tx(uint32_t addr, uint32_t bytes) {
    asm volatile("mbarrier.arrive.expect_tx.shared.b64 _, [%0], %1;"
                 :: "r"(addr), "r"(bytes) : "memory");
}
__device__ __forceinline__ void bulk_g2s_ef(uint32_t dst_smem, const void* gsrc,
                                            uint32_t bytes, uint32_t mbar) {
    unsigned long long pol;
    asm volatile("createpolicy.fractional.L2::evict_first.b64 %0, 1.0;" : "=l"(pol));
    asm volatile(
        "cp.async.bulk.shared::cta.global.mbarrier::complete_tx::bytes.L2::cache_hint "
        "[%0], [%1], %2, [%3], %4;"
        :: "r"(dst_smem), "l"(gsrc), "r"(bytes), "r"(mbar), "l"(pol) : "memory");
}
__device__ __forceinline__ void mbar_wait(uint32_t addr, uint32_t phase) {
    asm volatile(
        "{\n\t"
        ".reg .pred P;\n\t"
        "W%=:\n\t"
        "mbarrier.try_wait.parity.acquire.cta.shared::cta.b64 P, [%0], %1, 0x989680;\n\t"
        "@!P bra W%=;\n\t"
        "}"
        :: "r"(addr), "r"(phase) : "memory");
}
__device__ __forceinline__ unsigned int ld_acquire(const unsigned int* p) {
    unsigned int v;
    asm volatile("ld.acquire.gpu.u32 %0, [%1];" : "=r"(v) : "l"(p) : "memory");
    return v;
}
struct U64x4 { unsigned long long a, b, c, d; };
__device__ __forceinline__ U64x4 ldg32_evict_last(const void* p) {
    U64x4 v;
    asm volatile("ld.global.nc.L2::evict_last.v4.b64 {%0,%1,%2,%3}, [%4];"
                 : "=l"(v.a), "=l"(v.b), "=l"(v.c), "=l"(v.d) : "l"(p));
    return v;
}

// ---------------------------------------------------------------------------
// Fused kernel: every CTA stages its x row (evict-first TMA) immediately;
// CTAs 0..928 scan one fc1 tile (evict_last -> L2-resident across replays,
// so the scan is an L2-hit pass ~4us that hides under wave-1 staging);
// all CTAs wait on g_done, then gather. Counters self-reset by the last CTA.
// ---------------------------------------------------------------------------
__global__ __launch_bounds__(256, 8)
void fused_policy_kernel(const float* __restrict__ x,
                         const unsigned char* __restrict__ fc1b,
                         float* __restrict__ out) {
    __shared__ __align__(128) float row[FLAT];           // 20 KB
    __shared__ __align__(8) unsigned long long mbar;

    const int tid = threadIdx.x;
    const int bid = blockIdx.x;
    const uint32_t mbar_a = smem_u32(&mbar);
    const uint32_t row_a  = smem_u32(row);

    if (tid == 0) mbar_init(mbar_a, 1);
    __syncthreads();
    if (tid == 0) {
        mbar_expect_tx(mbar_a, ROW_BYTES);
        bulk_g2s_ef(row_a, x + (size_t)bid * FLAT, ROW_BYTES, mbar_a);
    }

    // ---- scan phase (first NSCAN blocks only; L2-hit after first replay) ----
    if (bid < NSCAN) {
        const int base = bid * 1280 + tid;               // 32B-chunk index

        U64x4 v0 = ldg32_evict_last(fc1b + (size_t)(base       ) * 32);
        U64x4 v1 = ldg32_evict_last(fc1b + (size_t)(base +  256) * 32);
        U64x4 v2 = ldg32_evict_last(fc1b + (size_t)(base +  512) * 32);
        U64x4 v3 = ldg32_evict_last(fc1b + (size_t)(base +  768) * 32);
        U64x4 v4 = ldg32_evict_last(fc1b + (size_t)(base + 1024) * 32);

        #pragma unroll
        for (int j = 0; j < 5; j++) {
            U64x4 v = (j == 0) ? v0 : (j == 1) ? v1 : (j == 2) ? v2 : (j == 3) ? v3 : v4;
            if (v.a | v.b | v.c | v.d) {   // <=1858 hits in 9.5M elems
                const long long e = ((long long)base + j * 256) * 8;   // float idx
                unsigned long long w[4] = { v.a, v.b, v.c, v.d };
                #pragma unroll
                for (int q = 0; q < 4; q++) {
                    if ((unsigned)(w[q] & 0xffffffffu)) {
                        long long ek = e + 2 * q;
                        g_idx[(int)(ek % NMOVES)] = (int)(ek / NMOVES);
                    }
                    if ((unsigned)(w[q] >> 32)) {
                        long long ek = e + 2 * q + 1;
                        g_idx[(int)(ek % NMOVES)] = (int)(ek / NMOVES);
                    }
                }
            }
        }
        __syncthreads();
        if (tid == 0) {
            __threadfence();                 // release g_idx writes
            atomicAdd(&g_done, 1u);
        }
    }

    // ---- wait for all scan tiles (wave-1 overlaps its TMA; waves>=2 instant)
    if (tid == 0) {
        while (ld_acquire(&g_done) != NSCAN) __nanosleep(64);
    }
    __syncthreads();

    // ---- gather (proven engine) ----
    const int2* idxp = reinterpret_cast<const int2*>(g_idx);
    const int2 i0 = idxp[tid];
    const int2 i1 = idxp[tid + 256];
    const int2 i2 = idxp[tid + 512];
    const bool has3 = tid < (NMOVES / 2 - 768);          // 161 threads
    int2 i3 = make_int2(0, 0);
    if (has3) i3 = idxp[tid + 768];

    mbar_wait(mbar_a, 0);

    float2* o = reinterpret_cast<float2*>(out + (size_t)bid * NMOVES);
    float2 v;
    v.x = row[i0.x]; v.y = row[i0.y]; __stcs(o + tid,       v);
    v.x = row[i1.x]; v.y = row[i1.y]; __stcs(o + tid + 256, v);
    v.x = row[i2.x]; v.y = row[i2.y]; __stcs(o + tid + 512, v);
    if (has3) {
        v.x = row[i3.x]; v.y = row[i3.y]; __stcs(o + tid + 768, v);
    }

    // ---- self-reset for the next replay (no memset node) ----
    // Every block increments g_passed after passing the wait; the last one
    // (all waiters provably gone) zeroes both counters.
    if (tid == 0) {
        unsigned int old = atomicAdd(&g_passed, 1u);
        if (old == (unsigned)(BATCH - 1)) {
            g_done = 0u;
            g_passed = 0u;
            __threadfence();
        }
    }
}

extern "C" void kernel_launch(void* const* d_in, const int* in_sizes, int n_in,
                              void* d_out, int out_size) {
    const float* x   = (const float*)d_in[0];   // [16384, 80, 8, 8] fp32
    const float* fc1 = (const float*)d_in[1];   // [5120, 1858] fp32
    float* out = (float*)d_out;                 // [16384, 1858] fp32

    fused_policy_kernel<<<BATCH, 256>>>(
        x, reinterpret_cast<const unsigned char*>(fc1), out);
}

// round 14
// speedup vs baseline: 1.1043x; 1.1043x over previous
#include <cuda_runtime.h>
#include <cuda_bf16.h>
#include <cstdint>

#define PLANES 80
#define FLAT   5120      // 80 * 64
#define NMOVES 1858
#define BATCH  16384
#define ROW_BYTES (FLAT * 4)   // 20480

#define TOTAL_CHUNKS (FLAT * NMOVES / 8)   // 32B chunks: 1,189,120
#define BUILD_GRID   465                    // 465*256*10 = 1,190,400 >= TOTAL_CHUNKS

// move -> flat-index map, rebuilt every launch (deterministic per call).
__device__ __align__(16) int g_idx[NMOVES];

// ---------------------------------------------------------------------------
// PTX helpers
// ---------------------------------------------------------------------------
__device__ __forceinline__ uint32_t smem_u32(const void* p) {
    uint32_t a;
    asm("{ .reg .u64 t; cvta.to.shared.u64 t, %1; cvt.u32.u64 %0, t; }"
        : "=r"(a) : "l"(p));
    return a;
}
__device__ __forceinline__ void mbar_init(uint32_t addr, uint32_t count) {
    asm volatile("mbarrier.init.shared.b64 [%0], %1;" :: "r"(addr), "r"(count) : "memory");
}
__device__ __forceinline__ void mbar_expect_tx(uint32_t addr, uint32_t bytes) {
    asm volatile("mbarrier.arrive.expect_tx.shared.b64 _, [%0], %1;"
                 :: "r"(addr), "r"(bytes) : "memory");
}
// bulk copy with evict-first L2 policy: x is single-use streaming data, so it
// must NOT displace the L2-resident fc1 between graph replays.
__device__ __forceinline__ void bulk_g2s_ef(uint32_t dst_smem, const void* gsrc,
                                            uint32_t bytes, uint32_t mbar) {
    unsigned long long pol;
    asm volatile("createpolicy.fractional.L2::evict_first.b64 %0, 1.0;" : "=l"(pol));
    asm volatile(
        "cp.async.bulk.shared::cta.global.mbarrier::complete_tx::bytes.L2::cache_hint "
        "[%0], [%1], %2, [%3], %4;"
        :: "r"(dst_smem), "l"(gsrc), "r"(bytes), "r"(mbar), "l"(pol) : "memory");
}
__device__ __forceinline__ void mbar_wait(uint32_t addr, uint32_t phase) {
    asm volatile(
        "{\n\t"
        ".reg .pred P;\n\t"
        "W%=:\n\t"
        "mbarrier.try_wait.parity.acquire.cta.shared::cta.b64 P, [%0], %1, 0x989680;\n\t"
        "@!P bra W%=;\n\t"
        "}"
        :: "r"(addr), "r"(phase) : "memory");
}
// PDL controls
__device__ __forceinline__ void pdl_launch_dependents() {
    asm volatile("griddepcontrol.launch_dependents;" ::: "memory");
}
__device__ __forceinline__ void pdl_wait() {
    asm volatile("griddepcontrol.wait;" ::: "memory");
}
// 32B load with L2 evict_last (legal width on sm_103: .v4.b64)
struct U64x4 { unsigned long long a, b, c, d; };
__device__ __forceinline__ U64x4 ldg32_evict_last(const void* p) {
    U64x4 v;
    asm volatile("ld.global.nc.L2::evict_last.v4.b64 {%0,%1,%2,%3}, [%4];"
                 : "=l"(v.a), "=l"(v.b), "=l"(v.c), "=l"(v.d) : "l"(p));
    return v;
}

// ---------------------------------------------------------------------------
// Kernel A: recover src index per move column from the 0/1 selection matrix.
// 465 blocks x 256 threads x 10 chunks of 32B (320B/thread in flight -> the
// L2-hit scan is latency-covered). evict_last keeps fc1 L2-resident across
// graph replays. Small grid (~3 CTAs/SM) lets PDL-launched gather CTAs
// co-reside and start their TMA staging during the scan.
// ---------------------------------------------------------------------------
__global__ __launch_bounds__(256)
void build_idx_kernel(const unsigned char* __restrict__ fc1b) {
    pdl_launch_dependents();

    const int base = blockIdx.x * 2560 + threadIdx.x;   // 2560 = 256*10 chunks

    #pragma unroll
    for (int j = 0; j < 10; j++) {
        const int t = base + j * 256;
        if (t < TOTAL_CHUNKS) {
            U64x4 v = ldg32_evict_last(fc1b + (size_t)t * 32);
            if (v.a | v.b | v.c | v.d) {   // rare: <=1858 hits in 9.5M elems
                const long long e = (long long)t * 8;    // float index
                unsigned long long w[4] = { v.a, v.b, v.c, v.d };
                #pragma unroll
                for (int q = 0; q < 4; q++) {
                    if ((unsigned)(w[q] & 0xffffffffu)) {
                        long long ek = e + 2 * q;
                        g_idx[(int)(ek % NMOVES)] = (int)(ek / NMOVES);
                    }
                    if ((unsigned)(w[q] >> 32)) {
                        long long ek = e + 2 * q + 1;
                        g_idx[(int)(ek % NMOVES)] = (int)(ek / NMOVES);
                    }
                }
            }
        }
    }
}

// ---------------------------------------------------------------------------
// Kernel B: out[b, m] = x[b, g_idx[m]].  (proven 61.5-62.6us engine)
// One CTA per batch row. Issue the x-row TMA copy (evict-first) BEFORE
// griddepcontrol.wait, wait for build, read indices, gather, .cs stores.
// ---------------------------------------------------------------------------
__global__ __launch_bounds__(256)
void policy_gather_kernel(const float* __restrict__ x,
                          float* __restrict__ out) {
    __shared__ __align__(128) float row[FLAT];           // 20 KB
    __shared__ __align__(8) unsigned long long mbar;

    const int tid = threadIdx.x;
    const int b = blockIdx.x;
    const uint32_t mbar_a = smem_u32(&mbar);
    const uint32_t row_a  = smem_u32(row);

    if (tid == 0) mbar_init(mbar_a, 1);
    __syncthreads();
    if (tid == 0) {
        mbar_expect_tx(mbar_a, ROW_BYTES);
        bulk_g2s_ef(row_a, x + (size_t)b * FLAT, ROW_BYTES, mbar_a);
    }

    // Block until the build grid has fully completed (g_idx visible).
    pdl_wait();

    // Preload gather indices (bulk copy possibly still in flight).
    const int2* idxp = reinterpret_cast<const int2*>(g_idx);
    const int2 i0 = idxp[tid];
    const int2 i1 = idxp[tid + 256];
    const int2 i2 = idxp[tid + 512];
    const bool has3 = tid < (NMOVES / 2 - 768);          // 161 threads
    int2 i3 = make_int2(0, 0);
    if (has3) i3 = idxp[tid + 768];

    mbar_wait(mbar_a, 0);

    float2* o = reinterpret_cast<float2*>(out + (size_t)b * NMOVES);
    float2 v;
    v.x = row[i0.x]; v.y = row[i0.y]; __stcs(o + tid,       v);
    v.x = row[i1.x]; v.y = row[i1.y]; __stcs(o + tid + 256, v);
    v.x = row[i2.x]; v.y = row[i2.y]; __stcs(o + tid + 512, v);
    if (has3) {
        v.x = row[i3.x]; v.y = row[i3.y]; __stcs(o + tid + 768, v);
    }
}

extern "C" void kernel_launch(void* const* d_in, const int* in_sizes, int n_in,
                              void* d_out, int out_size) {
    const float* x   = (const float*)d_in[0];   // [16384, 80, 8, 8] fp32
    const float* fc1 = (const float*)d_in[1];   // [5120, 1858] fp32
    float* out = (float*)d_out;                 // [16384, 1858] fp32

    // A: rebuild the selection index (L2-resident scan, high MLP, small grid).
    build_idx_kernel<<<BUILD_GRID, 256>>>(
        reinterpret_cast<const unsigned char*>(fc1));

    // B: gather with programmatic dependent launch (prologue overlaps build).
    cudaLaunchConfig_t cfg = {};
    cfg.gridDim  = dim3(BATCH);
    cfg.blockDim = dim3(256);
    cfg.dynamicSmemBytes = 0;
    cfg.stream = 0;
    cudaLaunchAttribute attr[1];
    attr[0].id = cudaLaunchAttributeProgrammaticStreamSerialization;
    attr[0].val.programmaticStreamSerializationAllowed = 1;
    cfg.attrs = attr;
    cfg.numAttrs = 1;
    cudaLaunchKernelEx(&cfg, policy_gather_kernel, x, out);
}

// round 15
// speedup vs baseline: 1.1217x; 1.0158x over previous
#include <cuda_runtime.h>
#include <cuda_bf16.h>
#include <cstdint>

#define PLANES 80
#define FLAT   5120      // 80 * 64
#define NMOVES 1858
#define BATCH  16384
#define ROW_BYTES (FLAT * 4)   // 20480
#define GTHREADS 128           // gather block size: 11 CTAs/SM (smem-limited)
#define NPAIRS  (NMOVES / 2)   // 929 float2 pairs per row

// move -> flat-index map, rebuilt every launch (deterministic per call).
__device__ __align__(16) int g_idx[NMOVES];

// ---------------------------------------------------------------------------
// PTX helpers
// ---------------------------------------------------------------------------
__device__ __forceinline__ uint32_t smem_u32(const void* p) {
    uint32_t a;
    asm("{ .reg .u64 t; cvta.to.shared.u64 t, %1; cvt.u32.u64 %0, t; }"
        : "=r"(a) : "l"(p));
    return a;
}
__device__ __forceinline__ void mbar_init(uint32_t addr, uint32_t count) {
    asm volatile("mbarrier.init.shared.b64 [%0], %1;" :: "r"(addr), "r"(count) : "memory");
}
__device__ __forceinline__ void mbar_expect_tx(uint32_t addr, uint32_t bytes) {
    asm volatile("mbarrier.arrive.expect_tx.shared.b64 _, [%0], %1;"
                 :: "r"(addr), "r"(bytes) : "memory");
}
// bulk copy with evict-first L2 policy: x is single-use streaming data, so it
// must NOT displace the L2-resident fc1 between graph replays.
__device__ __forceinline__ void bulk_g2s_ef(uint32_t dst_smem, const void* gsrc,
                                            uint32_t bytes, uint32_t mbar) {
    unsigned long long pol;
    asm volatile("createpolicy.fractional.L2::evict_first.b64 %0, 1.0;" : "=l"(pol));
    asm volatile(
        "cp.async.bulk.shared::cta.global.mbarrier::complete_tx::bytes.L2::cache_hint "
        "[%0], [%1], %2, [%3], %4;"
        :: "r"(dst_smem), "l"(gsrc), "r"(bytes), "r"(mbar), "l"(pol) : "memory");
}
__device__ __forceinline__ void mbar_wait(uint32_t addr, uint32_t phase) {
    asm volatile(
        "{\n\t"
        ".reg .pred P;\n\t"
        "W%=:\n\t"
        "mbarrier.try_wait.parity.acquire.cta.shared::cta.b64 P, [%0], %1, 0x989680;\n\t"
        "@!P bra W%=;\n\t"
        "}"
        :: "r"(addr), "r"(phase) : "memory");
}
// PDL controls
__device__ __forceinline__ void pdl_launch_dependents() {
    asm volatile("griddepcontrol.launch_dependents;" ::: "memory");
}
__device__ __forceinline__ void pdl_wait() {
    asm volatile("griddepcontrol.wait;" ::: "memory");
}
// 32B load with L2 evict_last (legal width on sm_103: .v4.b64)
struct U64x4 { unsigned long long a, b, c, d; };
__device__ __forceinline__ U64x4 ldg32_evict_last(const void* p) {
    U64x4 v;
    asm volatile("ld.global.nc.L2::evict_last.v4.b64 {%0,%1,%2,%3}, [%4];"
                 : "=l"(v.a), "=l"(v.b), "=l"(v.c), "=l"(v.d) : "l"(p));
    return v;
}

// ---------------------------------------------------------------------------
// Kernel A (exact R12 config, proven best): 929 blocks x 256 threads x
// 5 chunks of 32B = 38,051,840 B exactly. evict_last keeps fc1 L2-resident
// across graph replays -> scan runs at L2 speed on replays.
// ---------------------------------------------------------------------------
__global__ __launch_bounds__(256)
void build_idx_kernel(const unsigned char* __restrict__ fc1b) {
    pdl_launch_dependents();

    const int base = blockIdx.x * 1280 + threadIdx.x;   // 1280 = 256*5 chunks

    U64x4 v0 = ldg32_evict_last(fc1b + (size_t)(base       ) * 32);
    U64x4 v1 = ldg32_evict_last(fc1b + (size_t)(base +  256) * 32);
    U64x4 v2 = ldg32_evict_last(fc1b + (size_t)(base +  512) * 32);
    U64x4 v3 = ldg32_evict_last(fc1b + (size_t)(base +  768) * 32);
    U64x4 v4 = ldg32_evict_last(fc1b + (size_t)(base + 1024) * 32);

    #pragma unroll
    for (int j = 0; j < 5; j++) {
        U64x4 v = (j == 0) ? v0 : (j == 1) ? v1 : (j == 2) ? v2 : (j == 3) ? v3 : v4;
        if (v.a | v.b | v.c | v.d) {   // rare: <=1858 hits in 9.5M elems
            const long long e = ((long long)base + j * 256) * 8;  // float index
            unsigned long long w[4] = { v.a, v.b, v.c, v.d };
            #pragma unroll
            for (int q = 0; q < 4; q++) {
                if ((unsigned)(w[q] & 0xffffffffu)) {
                    long long ek = e + 2 * q;
                    g_idx[(int)(ek % NMOVES)] = (int)(ek / NMOVES);
                }
                if ((unsigned)(w[q] >> 32)) {
                    long long ek = e + 2 * q + 1;
                    g_idx[(int)(ek % NMOVES)] = (int)(ek / NMOVES);
                }
            }
        }
    }
}

// ---------------------------------------------------------------------------
// Kernel B: out[b, m] = x[b, g_idx[m]].
// 128-thread blocks -> smem-limited 11 CTAs/SM -> 11 concurrent 20KB TMA row
// copies per SM (vs 8 with 256-thr blocks): more staging bytes in flight.
// Each thread handles 8 pair-slots: tid + k*128 (k=0..7; k=7 only tid<33).
// ---------------------------------------------------------------------------
__global__ __launch_bounds__(GTHREADS)
void policy_gather_kernel(const float* __restrict__ x,
                          float* __restrict__ out) {
    __shared__ __align__(128) float row[FLAT];           // 20 KB
    __shared__ __align__(8) unsigned long long mbar;

    const int tid = threadIdx.x;
    const int b = blockIdx.x;
    const uint32_t mbar_a = smem_u32(&mbar);
    const uint32_t row_a  = smem_u32(row);

    if (tid == 0) mbar_init(mbar_a, 1);
    __syncthreads();
    if (tid == 0) {
        mbar_expect_tx(mbar_a, ROW_BYTES);
        bulk_g2s_ef(row_a, x + (size_t)b * FLAT, ROW_BYTES, mbar_a);
    }

    // Block until the build grid has fully completed (g_idx visible).
    pdl_wait();

    // Preload gather indices (bulk copy possibly still in flight).
    const int2* idxp = reinterpret_cast<const int2*>(g_idx);
    int2 idx[8];
    #pragma unroll
    for (int k = 0; k < 7; k++) idx[k] = idxp[tid + k * GTHREADS];
    const bool has7 = tid < (NPAIRS - 7 * GTHREADS);     // 33 threads
    idx[7] = has7 ? idxp[tid + 7 * GTHREADS] : make_int2(0, 0);

    mbar_wait(mbar_a, 0);

    float2* o = reinterpret_cast<float2*>(out + (size_t)b * NMOVES);
    #pragma unroll
    for (int k = 0; k < 7; k++) {
        float2 v;
        v.x = row[idx[k].x]; v.y = row[idx[k].y];
        __stcs(o + tid + k * GTHREADS, v);
    }
    if (has7) {
        float2 v;
        v.x = row[idx[7].x]; v.y = row[idx[7].y];
        __stcs(o + tid + 7 * GTHREADS, v);
    }
}

extern "C" void kernel_launch(void* const* d_in, const int* in_sizes, int n_in,
                              void* d_out, int out_size) {
    const float* x   = (const float*)d_in[0];   // [16384, 80, 8, 8] fp32
    const float* fc1 = (const float*)d_in[1];   // [5120, 1858] fp32
    float* out = (float*)d_out;                 // [16384, 1858] fp32

    // A: rebuild the selection index (R12-proven config, L2-pinned).
    build_idx_kernel<<<929, 256>>>(reinterpret_cast<const unsigned char*>(fc1));

    // B: gather with programmatic dependent launch (prologue overlaps build).
    cudaLaunchConfig_t cfg = {};
    cfg.gridDim  = dim3(BATCH);
    cfg.blockDim = dim3(GTHREADS);
    cfg.dynamicSmemBytes = 0;
    cfg.stream = 0;
    cudaLaunchAttribute attr[1];
    attr[0].id = cudaLaunchAttributeProgrammaticStreamSerialization;
    attr[0].val.programmaticStreamSerializationAllowed = 1;
    cfg.attrs = attr;
    cfg.numAttrs = 1;
    cudaLaunchKernelEx(&cfg, policy_gather_kernel, x, out);
}

// round 16
// speedup vs baseline: 1.1346x; 1.0115x over previous
#include <cuda_runtime.h>
#include <cuda_bf16.h>
#include <cstdint>

#define PLANES 80
#define FLAT   5120      // 80 * 64
#define NMOVES 1858
#define BATCH  16384
#define ROW_BYTES (FLAT * 4)   // 20480

// move -> flat-index map, rebuilt every launch (deterministic per call).
__device__ __align__(16) int g_idx[NMOVES];

// ---------------------------------------------------------------------------
// PTX helpers
// ---------------------------------------------------------------------------
__device__ __forceinline__ uint32_t smem_u32(const void* p) {
    uint32_t a;
    asm("{ .reg .u64 t; cvta.to.shared.u64 t, %1; cvt.u32.u64 %0, t; }"
        : "=r"(a) : "l"(p));
    return a;
}
__device__ __forceinline__ void mbar_init(uint32_t addr, uint32_t count) {
    asm volatile("mbarrier.init.shared.b64 [%0], %1;" :: "r"(addr), "r"(count) : "memory");
}
__device__ __forceinline__ void mbar_expect_tx(uint32_t addr, uint32_t bytes) {
    asm volatile("mbarrier.arrive.expect_tx.shared.b64 _, [%0], %1;"
                 :: "r"(addr), "r"(bytes) : "memory");
}
// bulk copy with evict-first L2 policy: x is single-use streaming data, so it
// must NOT displace the L2-resident fc1 between graph replays.
__device__ __forceinline__ void bulk_g2s_ef(uint32_t dst_smem, const void* gsrc,
                                            uint32_t bytes, uint32_t mbar) {
    unsigned long long pol;
    asm volatile("createpolicy.fractional.L2::evict_first.b64 %0, 1.0;" : "=l"(pol));
    asm volatile(
        "cp.async.bulk.shared::cta.global.mbarrier::complete_tx::bytes.L2::cache_hint "
        "[%0], [%1], %2, [%3], %4;"
        :: "r"(dst_smem), "l"(gsrc), "r"(bytes), "r"(mbar), "l"(pol) : "memory");
}
__device__ __forceinline__ void mbar_wait(uint32_t addr, uint32_t phase) {
    asm volatile(
        "{\n\t"
        ".reg .pred P;\n\t"
        "W%=:\n\t"
        "mbarrier.try_wait.parity.acquire.cta.shared::cta.b64 P, [%0], %1, 0x989680;\n\t"
        "@!P bra W%=;\n\t"
        "}"
        :: "r"(addr), "r"(phase) : "memory");
}
// PDL controls
__device__ __forceinline__ void pdl_launch_dependents() {
    asm volatile("griddepcontrol.launch_dependents;" ::: "memory");
}
__device__ __forceinline__ void pdl_wait() {
    asm volatile("griddepcontrol.wait;" ::: "memory");
}
// 32B load with L2 evict_last (legal width on sm_103: .v4.b64)
struct U64x4 { unsigned long long a, b, c, d; };
__device__ __forceinline__ U64x4 ldg32_evict_last(const void* p) {
    U64x4 v;
    asm volatile("ld.global.nc.L2::evict_last.v4.b64 {%0,%1,%2,%3}, [%4];"
                 : "=l"(v.a), "=l"(v.b), "=l"(v.c), "=l"(v.d) : "l"(p));
    return v;
}

// ---------------------------------------------------------------------------
// Kernel A: recover src index per move column from the 0/1 selection matrix.
// Finer blocks for better tail balance + earlier slot release to the PDL
// dependent grid: 1858 blocks x 128 threads x 5 chunks of 32B =
// 1,189,120 chunks = 38,051,840 B exactly. evict_last keeps fc1 L2-resident
// across graph replays -> scan runs at L2 speed on replays.
// ---------------------------------------------------------------------------
__global__ __launch_bounds__(128)
void build_idx_kernel(const unsigned char* __restrict__ fc1b) {
    pdl_launch_dependents();

    const int base = blockIdx.x * 640 + threadIdx.x;    // 640 = 128*5 chunks

    U64x4 v0 = ldg32_evict_last(fc1b + (size_t)(base      ) * 32);
    U64x4 v1 = ldg32_evict_last(fc1b + (size_t)(base + 128) * 32);
    U64x4 v2 = ldg32_evict_last(fc1b + (size_t)(base + 256) * 32);
    U64x4 v3 = ldg32_evict_last(fc1b + (size_t)(base + 384) * 32);
    U64x4 v4 = ldg32_evict_last(fc1b + (size_t)(base + 512) * 32);

    #pragma unroll
    for (int j = 0; j < 5; j++) {
        U64x4 v = (j == 0) ? v0 : (j == 1) ? v1 : (j == 2) ? v2 : (j == 3) ? v3 : v4;
        if (v.a | v.b | v.c | v.d) {   // rare: <=1858 hits in 9.5M elems
            const long long e = ((long long)base + j * 128) * 8;  // float index
            unsigned long long w[4] = { v.a, v.b, v.c, v.d };
            #pragma unroll
            for (int q = 0; q < 4; q++) {
                if ((unsigned)(w[q] & 0xffffffffu)) {
                    long long ek = e + 2 * q;
                    g_idx[(int)(ek % NMOVES)] = (int)(ek / NMOVES);
                }
                if ((unsigned)(w[q] >> 32)) {
                    long long ek = e + 2 * q + 1;
                    g_idx[(int)(ek % NMOVES)] = (int)(ek / NMOVES);
                }
            }
        }
    }
}

// ---------------------------------------------------------------------------
// Kernel B (byte-identical to R12's proven engine): out[b,m] = x[b, g_idx[m]].
// One CTA per batch row. Issue the x-row TMA copy (evict-first) BEFORE
// griddepcontrol.wait, wait for build, read indices, gather, .cs stores.
// ---------------------------------------------------------------------------
__global__ __launch_bounds__(256)
void policy_gather_kernel(const float* __restrict__ x,
                          float* __restrict__ out) {
    __shared__ __align__(128) float row[FLAT];           // 20 KB
    __shared__ __align__(8) unsigned long long mbar;

    const int tid = threadIdx.x;
    const int b = blockIdx.x;
    const uint32_t mbar_a = smem_u32(&mbar);
    const uint32_t row_a  = smem_u32(row);

    if (tid == 0) mbar_init(mbar_a, 1);
    __syncthreads();
    if (tid == 0) {
        mbar_expect_tx(mbar_a, ROW_BYTES);
        bulk_g2s_ef(row_a, x + (size_t)b * FLAT, ROW_BYTES, mbar_a);
    }

    // Block until the build grid has fully completed (g_idx visible).
    pdl_wait();

    // Preload gather indices (bulk copy possibly still in flight).
    const int2* idxp = reinterpret_cast<const int2*>(g_idx);
    const int2 i0 = idxp[tid];
    const int2 i1 = idxp[tid + 256];
    const int2 i2 = idxp[tid + 512];
    const bool has3 = tid < (NMOVES / 2 - 768);          // 161 threads
    int2 i3 = make_int2(0, 0);
    if (has3) i3 = idxp[tid + 768];

    mbar_wait(mbar_a, 0);

    float2* o = reinterpret_cast<float2*>(out + (size_t)b * NMOVES);
    float2 v;
    v.x = row[i0.x]; v.y = row[i0.y]; __stcs(o + tid,       v);
    v.x = row[i1.x]; v.y = row[i1.y]; __stcs(o + tid + 256, v);
    v.x = row[i2.x]; v.y = row[i2.y]; __stcs(o + tid + 512, v);
    if (has3) {
        v.x = row[i3.x]; v.y = row[i3.y]; __stcs(o + tid + 768, v);
    }
}

extern "C" void kernel_launch(void* const* d_in, const int* in_sizes, int n_in,
                              void* d_out, int out_size) {
    const float* x   = (const float*)d_in[0];   // [16384, 80, 8, 8] fp32
    const float* fc1 = (const float*)d_in[1];   // [5120, 1858] fp32
    float* out = (float*)d_out;                 // [16384, 1858] fp32

    // A: rebuild the selection index (L2-pinned scan, fine-grained blocks).
    build_idx_kernel<<<1858, 128>>>(reinterpret_cast<const unsigned char*>(fc1));

    // B: gather with programmatic dependent launch (prologue overlaps build).
    cudaLaunchConfig_t cfg = {};
    cfg.gridDim  = dim3(BATCH);
    cfg.blockDim = dim3(256);
    cfg.dynamicSmemBytes = 0;
    cfg.stream = 0;
    cudaLaunchAttribute attr[1];
    attr[0].id = cudaLaunchAttributeProgrammaticStreamSerialization;
    attr[0].val.programmaticStreamSerializationAllowed = 1;
    cfg.attrs = attr;
    cfg.numAttrs = 1;
    cudaLaunchKernelEx(&cfg, policy_gather_kernel, x, out);
}